// round 12
// baseline (speedup 1.0000x reference)
#include <cuda_runtime.h>
#include <cuda_bf16.h>
#include <cstdint>

#define NN 100000
#define NE 3200000
#define FIN 512
#define FH 256
#define FC 40
#define NPAD 100096          // 782 * 128

#define SCAN_B 1024
#define NSCANBLK ((NN + SCAN_B - 1) / SCAN_B)   // 98

typedef unsigned long long ull;

// ---------------- scratch (device globals; no allocation allowed) -----------
__device__ __align__(16) float g_support[(size_t)NN * FH];  // X@W1 (fp32)
__device__ __align__(16) float g_h[(size_t)NN * FH];        // relu(A support + b1)
__device__ __align__(16) float g_z[(size_t)NN * FC];        // h@W2
__device__ int   g_cnt[NN];
__device__ int   g_rowptr[NN + 1];
__device__ int   g_cursor[NN];
__device__ int   g_bsum[NSCANBLK];
__device__ __align__(16) int2  g_edge[NE];                  // (col, val bits)
// W1 split into bf16 hi/lo planes, transposed to [n][k]
__device__ __align__(16) __nv_bfloat16 g_wTh[(size_t)FH * FIN];
__device__ __align__(16) __nv_bfloat16 g_wTl[(size_t)FH * FIN];

// ---------------- packed f32x2 helpers ---------------------------------------
__device__ __forceinline__ ull pack2(float lo, float hi) {
    ull r; asm("mov.b64 %0,{%1,%2};" : "=l"(r) : "f"(lo), "f"(hi)); return r;
}
__device__ __forceinline__ ull ffma2(ull a, ull b, ull c) {
    ull r; asm("fma.rn.f32x2 %0,%1,%2,%3;" : "=l"(r) : "l"(a), "l"(b), "l"(c)); return r;
}
__device__ __forceinline__ float2 unpack2(ull v) {
    float2 f; asm("mov.b64 {%0,%1},%2;" : "=f"(f.x), "=f"(f.y) : "l"(v)); return f;
}

// ---------------- mma helpers -------------------------------------------------
__device__ __forceinline__ uint32_t smem_u32(const void* p) {
    uint32_t a;
    asm("{ .reg .u64 t; cvta.to.shared.u64 t, %1; cvt.u32.u64 %0, t; }" : "=r"(a) : "l"(p));
    return a;
}
__device__ __forceinline__ void ldm_x4(uint32_t* r, uint32_t addr) {
    asm volatile("ldmatrix.sync.aligned.m8n8.x4.shared.b16 {%0,%1,%2,%3}, [%4];"
                 : "=r"(r[0]), "=r"(r[1]), "=r"(r[2]), "=r"(r[3]) : "r"(addr));
}
__device__ __forceinline__ void mma_bf16(float* d, const uint32_t* a,
                                         uint32_t b0, uint32_t b1) {
    asm volatile("mma.sync.aligned.m16n8k16.row.col.f32.bf16.bf16.f32 "
                 "{%0,%1,%2,%3}, {%4,%5,%6,%7}, {%8,%9}, {%0,%1,%2,%3};"
                 : "+f"(d[0]), "+f"(d[1]), "+f"(d[2]), "+f"(d[3])
                 : "r"(a[0]), "r"(a[1]), "r"(a[2]), "r"(a[3]), "r"(b0), "r"(b1));
}
__device__ __forceinline__ void cp16(uint32_t dst, const void* src) {
    asm volatile("cp.async.cg.shared.global [%0], [%1], 16;" :: "r"(dst), "l"(src) : "memory");
}
#define CP_COMMIT() asm volatile("cp.async.commit_group;" ::: "memory")
#define CP_WAIT0()  asm volatile("cp.async.wait_group 0;" ::: "memory")

// ---------------- CSR build --------------------------------------------------
__global__ void k_zero_cnt() {
    for (int i = blockIdx.x * blockDim.x + threadIdx.x; i < NN; i += gridDim.x * blockDim.x)
        g_cnt[i] = 0;
}

__global__ void k_hist(const int* __restrict__ erow) {
    for (int e = blockIdx.x * blockDim.x + threadIdx.x; e < NE; e += gridDim.x * blockDim.x)
        atomicAdd(&g_cnt[erow[e]], 1);
}

__global__ void k_scan1() {
    __shared__ int sh[SCAN_B];
    int b = blockIdx.x, t = threadIdx.x;
    int i = b * SCAN_B + t;
    int v = (i < NN) ? g_cnt[i] : 0;
    sh[t] = v;
    __syncthreads();
    for (int off = 1; off < SCAN_B; off <<= 1) {
        int x = (t >= off) ? sh[t - off] : 0;
        __syncthreads();
        sh[t] += x;
        __syncthreads();
    }
    if (i < NN) g_rowptr[i] = sh[t] - v;
    if (t == SCAN_B - 1) g_bsum[b] = sh[t];
}

__global__ void k_scan2() {
    __shared__ int sh[128];
    int t = threadIdx.x;
    int v = (t < NSCANBLK) ? g_bsum[t] : 0;
    sh[t] = v;
    __syncthreads();
    for (int off = 1; off < 128; off <<= 1) {
        int x = (t >= off) ? sh[t - off] : 0;
        __syncthreads();
        sh[t] += x;
        __syncthreads();
    }
    if (t < NSCANBLK) g_bsum[t] = sh[t] - v;
    if (t == 127) g_rowptr[NN] = sh[127];
}

__global__ void k_scan3() {
    for (int i = blockIdx.x * blockDim.x + threadIdx.x; i < NN; i += gridDim.x * blockDim.x) {
        int v = g_rowptr[i] + g_bsum[i >> 10];
        g_rowptr[i] = v;
        g_cursor[i] = v;
    }
}

__global__ void k_scatter(const float* __restrict__ eval,
                          const int* __restrict__ erow,
                          const int* __restrict__ ecol) {
    for (int e = blockIdx.x * blockDim.x + threadIdx.x; e < NE; e += gridDim.x * blockDim.x) {
        int r = erow[e];
        int p = atomicAdd(&g_cursor[r], 1);
        g_edge[p] = make_int2(ecol[e], __float_as_int(eval[e]));
    }
}

// ---------------- W1 split: w1[512][256] -> wTh/wTl [256][512] bf16 ----------
__global__ void k_split_w(const float* __restrict__ w1) {
    int idx = blockIdx.x * blockDim.x + threadIdx.x;
    if (idx >= FIN * FH) return;
    int k = idx / FH, n = idx % FH;
    float w = w1[idx];
    __nv_bfloat16 hi = __float2bfloat16_rn(w);
    __nv_bfloat16 lo = __float2bfloat16_rn(w - __bfloat162float(hi));
    g_wTh[(size_t)n * FIN + k] = hi;
    g_wTl[(size_t)n * FIN + k] = lo;
}

// ---------------- GEMM1 (HMMA mma.sync, split-bf16): support = X @ W1 --------
// CTA tile: M=128, N=128 (grid.y=2 n-half), 128 threads / 4 warps.
// Warp tile 64x64 (wm=wid&1, wn=wid>>1): 4 m-frags x 8 n-frags.
// 80KB smem double-buffered -> 2 CTAs/SM. D = Xh*Wh + Xh*Wl + Xl*Wh.
#define RSTR 40                    // bf16 row stride (80B): conflict-free ldmatrix
#define A_PL (128 * RSTR * 2)      // 10240 B per A plane
#define B_PL (128 * RSTR * 2)      // 10240 B per B plane
#define OFF_AH 0
#define OFF_AL A_PL
#define OFF_BH (2 * A_PL)
#define OFF_BL (2 * A_PL + B_PL)
#define BUFSZ  (2 * A_PL + 2 * B_PL)   // 40960
#define SMEM_MMA (2 * BUFSZ)           // 81920

__global__ __launch_bounds__(128, 2) void k_gemm1_mma(const float* __restrict__ x) {
    extern __shared__ char smem[];
    const uint32_t sb = smem_u32(smem);
    const int tid = threadIdx.x;
    const int lane = tid & 31;
    const int wid = tid >> 5;          // 0..3
    const int wm = wid & 1;            // 2 x m64
    const int wn = wid >> 1;           // 2 x n64
    const int bm = blockIdx.x * 128;
    const int bn = blockIdx.y * 128;

    const int a_r  = (lane & 7) + (lane & 8);
    const int a_kb = (lane & 16) ? 16 : 0;
    const int b_r  = (lane & 7) + ((lane & 16) >> 1);
    const int b_kb = (lane & 8) << 1;

    float acc[4][8][4];
#pragma unroll
    for (int i = 0; i < 4; i++)
#pragma unroll
        for (int j = 0; j < 8; j++)
#pragma unroll
            for (int q = 0; q < 4; q++) acc[i][j][q] = 0.f;

    float4 areg[8];
    const float4 z4 = make_float4(0.f, 0.f, 0.f, 0.f);

    // ---- loaders (128 threads) ----
    auto ldgA = [&](int k0) {
#pragma unroll
        for (int i = 0; i < 8; i++) {
            int lin = tid + i * 128;        // 0..1023
            int row = lin >> 3, g = lin & 7;
            int gr = bm + row;
            areg[i] = (gr < NN) ? *(const float4*)&x[(size_t)gr * FIN + k0 + g * 4] : z4;
        }
    };
    auto stsA = [&](int buf) {
        char* base = smem + buf * BUFSZ;
#pragma unroll
        for (int i = 0; i < 8; i++) {
            int lin = tid + i * 128;
            int row = lin >> 3, g = lin & 7;
            float4 v = areg[i];
            __nv_bfloat16 h0 = __float2bfloat16_rn(v.x), h1 = __float2bfloat16_rn(v.y);
            __nv_bfloat16 h2 = __float2bfloat16_rn(v.z), h3 = __float2bfloat16_rn(v.w);
            __nv_bfloat16 l0 = __float2bfloat16_rn(v.x - __bfloat162float(h0));
            __nv_bfloat16 l1 = __float2bfloat16_rn(v.y - __bfloat162float(h1));
            __nv_bfloat16 l2 = __float2bfloat16_rn(v.z - __bfloat162float(h2));
            __nv_bfloat16 l3 = __float2bfloat16_rn(v.w - __bfloat162float(h3));
            uint32_t ph0 = ((uint32_t)__bfloat16_as_ushort(h1) << 16) | __bfloat16_as_ushort(h0);
            uint32_t ph1 = ((uint32_t)__bfloat16_as_ushort(h3) << 16) | __bfloat16_as_ushort(h2);
            uint32_t pl0 = ((uint32_t)__bfloat16_as_ushort(l1) << 16) | __bfloat16_as_ushort(l0);
            uint32_t pl1 = ((uint32_t)__bfloat16_as_ushort(l3) << 16) | __bfloat16_as_ushort(l2);
            int boff = row * (RSTR * 2) + g * 8;
            *(uint2*)(base + OFF_AH + boff) = make_uint2(ph0, ph1);
            *(uint2*)(base + OFF_AL + boff) = make_uint2(pl0, pl1);
        }
    };
    auto cpB = [&](int buf, int k0) {
        uint32_t bbase = sb + buf * BUFSZ;
#pragma unroll
        for (int i = 0; i < 4; i++) {
            int lin = tid + i * 128;        // 0..511
            int n = lin >> 2, c = lin & 3;
            uint32_t doff = n * (RSTR * 2) + c * 16;
            cp16(bbase + OFF_BH + doff, &g_wTh[(size_t)(bn + n) * FIN + k0 + c * 8]);
            cp16(bbase + OFF_BL + doff, &g_wTl[(size_t)(bn + n) * FIN + k0 + c * 8]);
        }
    };

    ldgA(0);
    cpB(0, 0);
    CP_COMMIT();
    stsA(0);
    CP_WAIT0();
    __syncthreads();

    int buf = 0;
    for (int t = 0; t < 16; t++) {
        if (t < 15) {
            ldgA((t + 1) * 32);
            cpB(buf ^ 1, (t + 1) * 32);
            CP_COMMIT();
        }
        const uint32_t cb = sb + buf * BUFSZ;
        const uint32_t ah_b = cb + OFF_AH, al_b = cb + OFF_AL;
        const uint32_t bh_b = cb + OFF_BH, bl_b = cb + OFF_BL;
#pragma unroll
        for (int ks = 0; ks < 2; ks++) {
            uint32_t Ah[4][4], Al[4][4];
#pragma unroll
            for (int mi = 0; mi < 4; mi++) {
                uint32_t off = (uint32_t)(wm * 64 + mi * 16 + a_r) * (RSTR * 2) + ks * 32 + a_kb;
                ldm_x4(Ah[mi], ah_b + off);
                ldm_x4(Al[mi], al_b + off);
            }
#pragma unroll
            for (int p = 0; p < 4; p++) {
                uint32_t bh[4], bl[4];
                uint32_t off = (uint32_t)(wn * 64 + p * 16 + b_r) * (RSTR * 2) + ks * 32 + b_kb;
                ldm_x4(bh, bh_b + off);
                ldm_x4(bl, bl_b + off);
#pragma unroll
                for (int mi = 0; mi < 4; mi++) {
                    mma_bf16(acc[mi][2 * p],     Ah[mi], bh[0], bh[1]);
                    mma_bf16(acc[mi][2 * p + 1], Ah[mi], bh[2], bh[3]);
                    mma_bf16(acc[mi][2 * p],     Ah[mi], bl[0], bl[1]);
                    mma_bf16(acc[mi][2 * p + 1], Ah[mi], bl[2], bl[3]);
                    mma_bf16(acc[mi][2 * p],     Al[mi], bh[0], bh[1]);
                    mma_bf16(acc[mi][2 * p + 1], Al[mi], bh[2], bh[3]);
                }
            }
        }
        if (t < 15) {
            stsA(buf ^ 1);
            CP_WAIT0();
        }
        __syncthreads();
        buf ^= 1;
    }

    const int m_base = bm + wm * 64;
    const int n_base = bn + wn * 64;
    const int rl = lane >> 2;
    const int cl = 2 * (lane & 3);
#pragma unroll
    for (int mi = 0; mi < 4; mi++) {
#pragma unroll
        for (int j = 0; j < 8; j++) {
            int r0 = m_base + mi * 16 + rl;
            int c = n_base + j * 8 + cl;
            if (r0 < NN)
                *(float2*)&g_support[(size_t)r0 * FH + c] =
                    make_float2(acc[mi][j][0], acc[mi][j][1]);
            int r1 = r0 + 8;
            if (r1 < NN)
                *(float2*)&g_support[(size_t)r1 * FH + c] =
                    make_float2(acc[mi][j][2], acc[mi][j][3]);
        }
    }
}

// ---------------- SpMM1: h = relu(A @ support + b1) --------------------------
__global__ __launch_bounds__(64) void k_spmm1(const float* __restrict__ b1) {
    __shared__ int   shc[64];
    __shared__ float shv[64];
    const int r = blockIdx.x;
    const int t = threadIdx.x;
    const int s = g_rowptr[r], e = g_rowptr[r + 1];
    ull acc0 = 0ULL, acc1 = 0ULL;
    for (int base = s; base < e; base += 64) {
        int idx = base + t;
        if (idx < e) {
            int2 cv = g_edge[idx];
            shc[t] = cv.x;
            shv[t] = __int_as_float(cv.y);
        }
        __syncthreads();
        int m = min(64, e - base);
#pragma unroll 8
        for (int i = 0; i < m; i++) {
            ulonglong2 v = *(const ulonglong2*)&g_support[(size_t)shc[i] * FH + 4 * t];
            ull s2 = pack2(shv[i], shv[i]);
            acc0 = ffma2(s2, v.x, acc0);
            acc1 = ffma2(s2, v.y, acc1);
        }
        __syncthreads();
    }
    float2 a0 = unpack2(acc0), a1 = unpack2(acc1);
    float4 bb = *(const float4*)&b1[4 * t];
    *(float4*)&g_h[(size_t)r * FH + 4 * t] =
        make_float4(fmaxf(a0.x + bb.x, 0.f), fmaxf(a0.y + bb.y, 0.f),
                    fmaxf(a1.x + bb.z, 0.f), fmaxf(a1.y + bb.w, 0.f));
}

// ---------------- GEMM2: z = h[NN,256] @ W2[256,40] --------------------------
#define Z_BK 32
#define HSTR 258

__global__ __launch_bounds__(256, 2) void k_gemm2(const float* __restrict__ w2) {
    __shared__ float shH[Z_BK * HSTR];
    __shared__ float shW[Z_BK * FC];
    const int rb = blockIdx.x * 256;
    const int tid = threadIdx.x;
    const int row = rb + tid;

    ull acc[20];
#pragma unroll
    for (int j = 0; j < 20; j++) acc[j] = 0ULL;

    const float4 z4 = make_float4(0.f, 0.f, 0.f, 0.f);

    for (int k0 = 0; k0 < FH; k0 += Z_BK) {
#pragma unroll
        for (int q = 0; q < 8; q++) {
            int L = tid + q * 256;
            int lr = L >> 3, c4 = L & 7;
            int gr = rb + lr;
            float4 v = (gr < NN) ? *(const float4*)&g_h[(size_t)gr * FH + k0 + c4 * 4] : z4;
            shH[(c4 * 4 + 0) * HSTR + lr] = v.x;
            shH[(c4 * 4 + 1) * HSTR + lr] = v.y;
            shH[(c4 * 4 + 2) * HSTR + lr] = v.z;
            shH[(c4 * 4 + 3) * HSTR + lr] = v.w;
        }
        {
            int L = tid;
            if (L < 320) {
                int rr = L / 10, c4 = L % 10;
                *(float4*)&shW[rr * FC + c4 * 4] =
                    *(const float4*)&w2[(size_t)(k0 + rr) * FC + c4 * 4];
            }
            L = tid + 256;
            if (L < 320) {
                int rr = L / 10, c4 = L % 10;
                *(float4*)&shW[rr * FC + c4 * 4] =
                    *(const float4*)&w2[(size_t)(k0 + rr) * FC + c4 * 4];
            }
        }
        __syncthreads();
#pragma unroll
        for (int kk = 0; kk < Z_BK; kk++) {
            float a = shH[kk * HSTR + tid];
            ull a2 = pack2(a, a);
#pragma unroll
            for (int p = 0; p < 10; p++) {
                ulonglong2 bb = *(const ulonglong2*)&shW[kk * FC + p * 4];
                acc[2 * p]     = ffma2(a2, bb.x, acc[2 * p]);
                acc[2 * p + 1] = ffma2(a2, bb.y, acc[2 * p + 1]);
            }
        }
        __syncthreads();
    }
    if (row < NN) {
#pragma unroll
        for (int p = 0; p < 10; p++) {
            float2 c0 = unpack2(acc[2 * p]), c1 = unpack2(acc[2 * p + 1]);
            *(float4*)&g_z[(size_t)row * FC + p * 4] = make_float4(c0.x, c0.y, c1.x, c1.y);
        }
    }
}

// ---------------- SpMM2 + bias + log_softmax ---------------------------------
__global__ __launch_bounds__(64) void k_spmm2(const float* __restrict__ b2,
                                              float* __restrict__ out) {
    __shared__ int   shc[64];
    __shared__ float shv[64];
    __shared__ float red[64];
    const int r = blockIdx.x;
    const int t = threadIdx.x;
    const int s = g_rowptr[r], e = g_rowptr[r + 1];
    float acc = 0.f;
    for (int base = s; base < e; base += 64) {
        int idx = base + t;
        if (idx < e) {
            int2 cv = g_edge[idx];
            shc[t] = cv.x;
            shv[t] = __int_as_float(cv.y);
        }
        __syncthreads();
        int m = min(64, e - base);
        if (t < FC) {
#pragma unroll 4
            for (int i = 0; i < m; i++)
                acc = fmaf(shv[i], g_z[(size_t)shc[i] * FC + t], acc);
        }
        __syncthreads();
    }
    float val = (t < FC) ? (acc + b2[t]) : 0.f;
    red[t] = (t < FC) ? val : -3.4e38f;
    __syncthreads();
#pragma unroll
    for (int off = 32; off > 0; off >>= 1) {
        if (t < off) red[t] = fmaxf(red[t], red[t + off]);
        __syncthreads();
    }
    float mx = red[0];
    __syncthreads();
    red[t] = (t < FC) ? expf(val - mx) : 0.f;
    __syncthreads();
#pragma unroll
    for (int off = 32; off > 0; off >>= 1) {
        if (t < off) red[t] += red[t + off];
        __syncthreads();
    }
    float lse = mx + logf(red[0]);
    if (t < FC) out[(size_t)r * FC + t] = val - lse;
}

// ---------------- launch -----------------------------------------------------
extern "C" void kernel_launch(void* const* d_in, const int* in_sizes, int n_in,
                              void* d_out, int out_size) {
    const float* x    = (const float*)d_in[0];
    const float* w1   = (const float*)d_in[1];
    const float* b1   = (const float*)d_in[2];
    const float* w2   = (const float*)d_in[3];
    const float* b2   = (const float*)d_in[4];
    const float* eval = (const float*)d_in[5];
    const int*   erow = (const int*)d_in[6];
    const int*   ecol = (const int*)d_in[7];
    float* out = (float*)d_out;

    static cudaStream_t s_side = nullptr;
    static cudaEvent_t  ev_fork = nullptr, ev_join = nullptr;
    static bool attr_set = false;
    if (!s_side) {
        cudaStreamCreateWithFlags(&s_side, cudaStreamNonBlocking);
        cudaEventCreateWithFlags(&ev_fork, cudaEventDisableTiming);
        cudaEventCreateWithFlags(&ev_join, cudaEventDisableTiming);
    }
    if (!attr_set) {
        cudaFuncSetAttribute(k_gemm1_mma, cudaFuncAttributeMaxDynamicSharedMemorySize, SMEM_MMA);
        attr_set = true;
    }

    // Fork: CSR build runs on s_side concurrently with split_w + GEMM1.
    cudaEventRecord(ev_fork, 0);
    cudaStreamWaitEvent(s_side, ev_fork, 0);

    k_zero_cnt<<<256, 256, 0, s_side>>>();
    k_hist<<<2048, 256, 0, s_side>>>(erow);
    k_scan1<<<NSCANBLK, SCAN_B, 0, s_side>>>();
    k_scan2<<<1, 128, 0, s_side>>>();
    k_scan3<<<196, 512, 0, s_side>>>();
    k_scatter<<<2048, 256, 0, s_side>>>(eval, erow, ecol);
    cudaEventRecord(ev_join, s_side);

    k_split_w<<<(FIN * FH + 255) / 256, 256>>>(w1);
    dim3 g1(NPAD / 128, 2);
    k_gemm1_mma<<<g1, 128, SMEM_MMA>>>(x);

    cudaStreamWaitEvent(0, ev_join, 0);

    k_spmm1<<<NN, 64>>>(b1);
    k_gemm2<<<(NN + 255) / 256, 256>>>(w2);
    k_spmm2<<<NN, 64>>>(b2, out);
}

// round 13
// speedup vs baseline: 1.0864x; 1.0864x over previous
#include <cuda_runtime.h>
#include <cuda_bf16.h>
#include <cstdint>

#define NN 100000
#define NE 3200000
#define FIN 512
#define FH 256
#define FC 40
#define NPAD 100096          // 782 * 128

#define SCAN_B 1024
#define NSCANBLK ((NN + SCAN_B - 1) / SCAN_B)   // 98

typedef unsigned long long ull;

// ---------------- scratch (device globals; no allocation allowed) -----------
__device__ __align__(16) float g_support[(size_t)NN * FH];  // X@W1 (fp32)
__device__ __align__(16) float g_h[(size_t)NN * FH];        // relu(A support + b1)
__device__ __align__(16) float g_z[(size_t)NN * FC];        // h@W2
__device__ int   g_cnt[NN];
__device__ int   g_rowptr[NN + 1];
__device__ int   g_cursor[NN];
__device__ int   g_bsum[NSCANBLK];
__device__ __align__(16) int2  g_edge[NE];                  // (col, val bits)
// W1 split into bf16 hi/lo planes, transposed to [n][k]
__device__ __align__(16) __nv_bfloat16 g_wTh[(size_t)FH * FIN];
__device__ __align__(16) __nv_bfloat16 g_wTl[(size_t)FH * FIN];

// ---------------- packed f32x2 helpers ---------------------------------------
__device__ __forceinline__ ull pack2(float lo, float hi) {
    ull r; asm("mov.b64 %0,{%1,%2};" : "=l"(r) : "f"(lo), "f"(hi)); return r;
}
__device__ __forceinline__ ull ffma2(ull a, ull b, ull c) {
    ull r; asm("fma.rn.f32x2 %0,%1,%2,%3;" : "=l"(r) : "l"(a), "l"(b), "l"(c)); return r;
}
__device__ __forceinline__ float2 unpack2(ull v) {
    float2 f; asm("mov.b64 {%0,%1},%2;" : "=f"(f.x), "=f"(f.y) : "l"(v)); return f;
}

// ---------------- mma helpers -------------------------------------------------
__device__ __forceinline__ uint32_t smem_u32(const void* p) {
    uint32_t a;
    asm("{ .reg .u64 t; cvta.to.shared.u64 t, %1; cvt.u32.u64 %0, t; }" : "=r"(a) : "l"(p));
    return a;
}
__device__ __forceinline__ void ldm_x4(uint32_t* r, uint32_t addr) {
    asm volatile("ldmatrix.sync.aligned.m8n8.x4.shared.b16 {%0,%1,%2,%3}, [%4];"
                 : "=r"(r[0]), "=r"(r[1]), "=r"(r[2]), "=r"(r[3]) : "r"(addr));
}
__device__ __forceinline__ void mma_bf16(float* d, const uint32_t* a,
                                         uint32_t b0, uint32_t b1) {
    asm volatile("mma.sync.aligned.m16n8k16.row.col.f32.bf16.bf16.f32 "
                 "{%0,%1,%2,%3}, {%4,%5,%6,%7}, {%8,%9}, {%0,%1,%2,%3};"
                 : "+f"(d[0]), "+f"(d[1]), "+f"(d[2]), "+f"(d[3])
                 : "r"(a[0]), "r"(a[1]), "r"(a[2]), "r"(a[3]), "r"(b0), "r"(b1));
}
__device__ __forceinline__ void cp16(uint32_t dst, const void* src) {
    asm volatile("cp.async.cg.shared.global [%0], [%1], 16;" :: "r"(dst), "l"(src) : "memory");
}
#define CP_COMMIT() asm volatile("cp.async.commit_group;" ::: "memory")
#define CP_WAIT0()  asm volatile("cp.async.wait_group 0;" ::: "memory")

// ---------------- CSR build --------------------------------------------------
__global__ void k_zero_cnt() {
    for (int i = blockIdx.x * blockDim.x + threadIdx.x; i < NN; i += gridDim.x * blockDim.x)
        g_cnt[i] = 0;
}

__global__ void k_hist(const int* __restrict__ erow) {
    for (int e = blockIdx.x * blockDim.x + threadIdx.x; e < NE; e += gridDim.x * blockDim.x)
        atomicAdd(&g_cnt[erow[e]], 1);
}

__global__ void k_scan1() {
    __shared__ int sh[SCAN_B];
    int b = blockIdx.x, t = threadIdx.x;
    int i = b * SCAN_B + t;
    int v = (i < NN) ? g_cnt[i] : 0;
    sh[t] = v;
    __syncthreads();
    for (int off = 1; off < SCAN_B; off <<= 1) {
        int x = (t >= off) ? sh[t - off] : 0;
        __syncthreads();
        sh[t] += x;
        __syncthreads();
    }
    if (i < NN) g_rowptr[i] = sh[t] - v;
    if (t == SCAN_B - 1) g_bsum[b] = sh[t];
}

__global__ void k_scan2() {
    __shared__ int sh[128];
    int t = threadIdx.x;
    int v = (t < NSCANBLK) ? g_bsum[t] : 0;
    sh[t] = v;
    __syncthreads();
    for (int off = 1; off < 128; off <<= 1) {
        int x = (t >= off) ? sh[t - off] : 0;
        __syncthreads();
        sh[t] += x;
        __syncthreads();
    }
    if (t < NSCANBLK) g_bsum[t] = sh[t] - v;
    if (t == 127) g_rowptr[NN] = sh[127];
}

__global__ void k_scan3() {
    for (int i = blockIdx.x * blockDim.x + threadIdx.x; i < NN; i += gridDim.x * blockDim.x) {
        int v = g_rowptr[i] + g_bsum[i >> 10];
        g_rowptr[i] = v;
        g_cursor[i] = v;
    }
}

__global__ void k_scatter(const float* __restrict__ eval,
                          const int* __restrict__ erow,
                          const int* __restrict__ ecol) {
    for (int e = blockIdx.x * blockDim.x + threadIdx.x; e < NE; e += gridDim.x * blockDim.x) {
        int r = erow[e];
        int p = atomicAdd(&g_cursor[r], 1);
        g_edge[p] = make_int2(ecol[e], __float_as_int(eval[e]));
    }
}

// ---------------- W1 split: w1[512][256] -> wTh/wTl [256][512] bf16 ----------
__global__ void k_split_w(const float* __restrict__ w1) {
    int idx = blockIdx.x * blockDim.x + threadIdx.x;
    if (idx >= FIN * FH) return;
    int k = idx / FH, n = idx % FH;
    float w = w1[idx];
    __nv_bfloat16 hi = __float2bfloat16_rn(w);
    __nv_bfloat16 lo = __float2bfloat16_rn(w - __bfloat162float(hi));
    g_wTh[(size_t)n * FIN + k] = hi;
    g_wTl[(size_t)n * FIN + k] = lo;
}

// ---------------- GEMM1 (HMMA mma.sync, split-bf16): support = X @ W1 --------
// R10-proven config: CTA tile M=128 x N=128 (nhalf selects n range),
// 256 threads / 8 warps: wm=wid&3 (4 x m32), wn=wid>>2 (2 x n64).
// Warp tile 32x64. 80KB smem double-buffered -> 2 CTAs/SM.
// D = Xh*Wh + Xh*Wl + Xl*Wh.
#define RSTR 40                    // bf16 row stride (80B): conflict-free ldmatrix
#define A_PL (128 * RSTR * 2)      // 10240 B per A plane
#define B_PL (128 * RSTR * 2)      // 10240 B per B plane
#define OFF_AH 0
#define OFF_AL A_PL
#define OFF_BH (2 * A_PL)
#define OFF_BL (2 * A_PL + B_PL)
#define BUFSZ  (2 * A_PL + 2 * B_PL)   // 40960
#define SMEM_MMA (2 * BUFSZ)           // 81920

__global__ __launch_bounds__(256, 2) void k_gemm1_mma(const float* __restrict__ x,
                                                      int nhalf) {
    extern __shared__ char smem[];
    const uint32_t sb = smem_u32(smem);
    const int tid = threadIdx.x;
    const int lane = tid & 31;
    const int wid = tid >> 5;
    const int wm = wid & 3;
    const int wn = wid >> 2;           // 0..1
    const int bm = blockIdx.x * 128;
    const int bn = nhalf * 128;

    const int a_r  = (lane & 7) + (lane & 8);
    const int a_kb = (lane & 16) ? 16 : 0;
    const int b_r  = (lane & 7) + ((lane & 16) >> 1);
    const int b_kb = (lane & 8) << 1;

    float acc[2][8][4];
#pragma unroll
    for (int i = 0; i < 2; i++)
#pragma unroll
        for (int j = 0; j < 8; j++)
#pragma unroll
            for (int q = 0; q < 4; q++) acc[i][j][q] = 0.f;

    float4 areg[4];
    const float4 z4 = make_float4(0.f, 0.f, 0.f, 0.f);

    auto ldgA = [&](int k0) {
#pragma unroll
        for (int i = 0; i < 4; i++) {
            int lin = tid + i * 256;
            int row = lin >> 3, g = lin & 7;
            int gr = bm + row;
            areg[i] = (gr < NN) ? *(const float4*)&x[(size_t)gr * FIN + k0 + g * 4] : z4;
        }
    };
    auto stsA = [&](int buf) {
        char* base = smem + buf * BUFSZ;
#pragma unroll
        for (int i = 0; i < 4; i++) {
            int lin = tid + i * 256;
            int row = lin >> 3, g = lin & 7;
            float4 v = areg[i];
            __nv_bfloat16 h0 = __float2bfloat16_rn(v.x), h1 = __float2bfloat16_rn(v.y);
            __nv_bfloat16 h2 = __float2bfloat16_rn(v.z), h3 = __float2bfloat16_rn(v.w);
            __nv_bfloat16 l0 = __float2bfloat16_rn(v.x - __bfloat162float(h0));
            __nv_bfloat16 l1 = __float2bfloat16_rn(v.y - __bfloat162float(h1));
            __nv_bfloat16 l2 = __float2bfloat16_rn(v.z - __bfloat162float(h2));
            __nv_bfloat16 l3 = __float2bfloat16_rn(v.w - __bfloat162float(h3));
            uint32_t ph0 = ((uint32_t)__bfloat16_as_ushort(h1) << 16) | __bfloat16_as_ushort(h0);
            uint32_t ph1 = ((uint32_t)__bfloat16_as_ushort(h3) << 16) | __bfloat16_as_ushort(h2);
            uint32_t pl0 = ((uint32_t)__bfloat16_as_ushort(l1) << 16) | __bfloat16_as_ushort(l0);
            uint32_t pl1 = ((uint32_t)__bfloat16_as_ushort(l3) << 16) | __bfloat16_as_ushort(l2);
            int boff = row * (RSTR * 2) + g * 8;
            *(uint2*)(base + OFF_AH + boff) = make_uint2(ph0, ph1);
            *(uint2*)(base + OFF_AL + boff) = make_uint2(pl0, pl1);
        }
    };
    auto cpB = [&](int buf, int k0) {
        uint32_t bbase = sb + buf * BUFSZ;
#pragma unroll
        for (int i = 0; i < 2; i++) {
            int lin = tid + i * 256;
            int n = lin >> 2, c = lin & 3;
            uint32_t doff = n * (RSTR * 2) + c * 16;
            cp16(bbase + OFF_BH + doff, &g_wTh[(size_t)(bn + n) * FIN + k0 + c * 8]);
            cp16(bbase + OFF_BL + doff, &g_wTl[(size_t)(bn + n) * FIN + k0 + c * 8]);
        }
    };

    ldgA(0);
    cpB(0, 0);
    CP_COMMIT();
    stsA(0);
    CP_WAIT0();
    __syncthreads();

    int buf = 0;
    for (int t = 0; t < 16; t++) {
        if (t < 15) {
            ldgA((t + 1) * 32);
            cpB(buf ^ 1, (t + 1) * 32);
            CP_COMMIT();
        }
        const uint32_t cb = sb + buf * BUFSZ;
        const uint32_t ah_b = cb + OFF_AH, al_b = cb + OFF_AL;
        const uint32_t bh_b = cb + OFF_BH, bl_b = cb + OFF_BL;
#pragma unroll
        for (int ks = 0; ks < 2; ks++) {
            uint32_t Ah[2][4], Al[2][4];
#pragma unroll
            for (int mi = 0; mi < 2; mi++) {
                uint32_t off = (uint32_t)(wm * 32 + mi * 16 + a_r) * (RSTR * 2) + ks * 32 + a_kb;
                ldm_x4(Ah[mi], ah_b + off);
                ldm_x4(Al[mi], al_b + off);
            }
#pragma unroll
            for (int p = 0; p < 4; p++) {
                uint32_t bh[4], bl[4];
                uint32_t off = (uint32_t)(wn * 64 + p * 16 + b_r) * (RSTR * 2) + ks * 32 + b_kb;
                ldm_x4(bh, bh_b + off);
                ldm_x4(bl, bl_b + off);
#pragma unroll
                for (int mi = 0; mi < 2; mi++) {
                    mma_bf16(acc[mi][2 * p],     Ah[mi], bh[0], bh[1]);
                    mma_bf16(acc[mi][2 * p + 1], Ah[mi], bh[2], bh[3]);
                    mma_bf16(acc[mi][2 * p],     Ah[mi], bl[0], bl[1]);
                    mma_bf16(acc[mi][2 * p + 1], Ah[mi], bl[2], bl[3]);
                    mma_bf16(acc[mi][2 * p],     Al[mi], bh[0], bh[1]);
                    mma_bf16(acc[mi][2 * p + 1], Al[mi], bh[2], bh[3]);
                }
            }
        }
        if (t < 15) {
            stsA(buf ^ 1);
            CP_WAIT0();
        }
        __syncthreads();
        buf ^= 1;
    }

    const int m_base = bm + wm * 32;
    const int n_base = bn + wn * 64;
    const int rl = lane >> 2;
    const int cl = 2 * (lane & 3);
#pragma unroll
    for (int mi = 0; mi < 2; mi++) {
#pragma unroll
        for (int j = 0; j < 8; j++) {
            int r0 = m_base + mi * 16 + rl;
            int c = n_base + j * 8 + cl;
            if (r0 < NN)
                *(float2*)&g_support[(size_t)r0 * FH + c] =
                    make_float2(acc[mi][j][0], acc[mi][j][1]);
            int r1 = r0 + 8;
            if (r1 < NN)
                *(float2*)&g_support[(size_t)r1 * FH + c] =
                    make_float2(acc[mi][j][2], acc[mi][j][3]);
        }
    }
}

// ---------------- SpMM1 (feature-half): h[:,half] = relu(A @ support[:,half] + b1) --
// 64 threads per row, 2 feats (8B, one f32x2) per lane per edge.
__global__ __launch_bounds__(64) void k_spmm1(const float* __restrict__ b1, int half) {
    __shared__ int   shc[64];
    __shared__ float shv[64];
    const int r = blockIdx.x;
    const int t = threadIdx.x;
    const int s = g_rowptr[r], e = g_rowptr[r + 1];
    const int off = half * 128 + 2 * t;
    ull acc = 0ULL;
    for (int base = s; base < e; base += 64) {
        int idx = base + t;
        if (idx < e) {
            int2 cv = g_edge[idx];
            shc[t] = cv.x;
            shv[t] = __int_as_float(cv.y);
        }
        __syncthreads();
        int m = min(64, e - base);
#pragma unroll 8
        for (int i = 0; i < m; i++) {
            ull v = *(const ull*)&g_support[(size_t)shc[i] * FH + off];
            acc = ffma2(pack2(shv[i], shv[i]), v, acc);
        }
        __syncthreads();
    }
    float2 a = unpack2(acc);
    float2 bb = *(const float2*)&b1[off];
    *(float2*)&g_h[(size_t)r * FH + off] =
        make_float2(fmaxf(a.x + bb.x, 0.f), fmaxf(a.y + bb.y, 0.f));
}

// ---------------- GEMM2: z = h[NN,256] @ W2[256,40] --------------------------
#define Z_BK 32
#define HSTR 258

__global__ __launch_bounds__(256, 2) void k_gemm2(const float* __restrict__ w2) {
    __shared__ float shH[Z_BK * HSTR];
    __shared__ float shW[Z_BK * FC];
    const int rb = blockIdx.x * 256;
    const int tid = threadIdx.x;
    const int row = rb + tid;

    ull acc[20];
#pragma unroll
    for (int j = 0; j < 20; j++) acc[j] = 0ULL;

    const float4 z4 = make_float4(0.f, 0.f, 0.f, 0.f);

    for (int k0 = 0; k0 < FH; k0 += Z_BK) {
#pragma unroll
        for (int q = 0; q < 8; q++) {
            int L = tid + q * 256;
            int lr = L >> 3, c4 = L & 7;
            int gr = rb + lr;
            float4 v = (gr < NN) ? *(const float4*)&g_h[(size_t)gr * FH + k0 + c4 * 4] : z4;
            shH[(c4 * 4 + 0) * HSTR + lr] = v.x;
            shH[(c4 * 4 + 1) * HSTR + lr] = v.y;
            shH[(c4 * 4 + 2) * HSTR + lr] = v.z;
            shH[(c4 * 4 + 3) * HSTR + lr] = v.w;
        }
        {
            int L = tid;
            if (L < 320) {
                int rr = L / 10, c4 = L % 10;
                *(float4*)&shW[rr * FC + c4 * 4] =
                    *(const float4*)&w2[(size_t)(k0 + rr) * FC + c4 * 4];
            }
            L = tid + 256;
            if (L < 320) {
                int rr = L / 10, c4 = L % 10;
                *(float4*)&shW[rr * FC + c4 * 4] =
                    *(const float4*)&w2[(size_t)(k0 + rr) * FC + c4 * 4];
            }
        }
        __syncthreads();
#pragma unroll
        for (int kk = 0; kk < Z_BK; kk++) {
            float a = shH[kk * HSTR + tid];
            ull a2 = pack2(a, a);
#pragma unroll
            for (int p = 0; p < 10; p++) {
                ulonglong2 bb = *(const ulonglong2*)&shW[kk * FC + p * 4];
                acc[2 * p]     = ffma2(a2, bb.x, acc[2 * p]);
                acc[2 * p + 1] = ffma2(a2, bb.y, acc[2 * p + 1]);
            }
        }
        __syncthreads();
    }
    if (row < NN) {
#pragma unroll
        for (int p = 0; p < 10; p++) {
            float2 c0 = unpack2(acc[2 * p]), c1 = unpack2(acc[2 * p + 1]);
            *(float4*)&g_z[(size_t)row * FC + p * 4] = make_float4(c0.x, c0.y, c1.x, c1.y);
        }
    }
}

// ---------------- SpMM2 + bias + log_softmax ---------------------------------
__global__ __launch_bounds__(64) void k_spmm2(const float* __restrict__ b2,
                                              float* __restrict__ out) {
    __shared__ int   shc[64];
    __shared__ float shv[64];
    __shared__ float red[64];
    const int r = blockIdx.x;
    const int t = threadIdx.x;
    const int s = g_rowptr[r], e = g_rowptr[r + 1];
    float acc = 0.f;
    for (int base = s; base < e; base += 64) {
        int idx = base + t;
        if (idx < e) {
            int2 cv = g_edge[idx];
            shc[t] = cv.x;
            shv[t] = __int_as_float(cv.y);
        }
        __syncthreads();
        int m = min(64, e - base);
        if (t < FC) {
#pragma unroll 4
            for (int i = 0; i < m; i++)
                acc = fmaf(shv[i], g_z[(size_t)shc[i] * FC + t], acc);
        }
        __syncthreads();
    }
    float val = (t < FC) ? (acc + b2[t]) : 0.f;
    red[t] = (t < FC) ? val : -3.4e38f;
    __syncthreads();
#pragma unroll
    for (int off = 32; off > 0; off >>= 1) {
        if (t < off) red[t] = fmaxf(red[t], red[t + off]);
        __syncthreads();
    }
    float mx = red[0];
    __syncthreads();
    red[t] = (t < FC) ? expf(val - mx) : 0.f;
    __syncthreads();
#pragma unroll
    for (int off = 32; off > 0; off >>= 1) {
        if (t < off) red[t] += red[t + off];
        __syncthreads();
    }
    float lse = mx + logf(red[0]);
    if (t < FC) out[(size_t)r * FC + t] = val - lse;
}

// ---------------- launch -----------------------------------------------------
extern "C" void kernel_launch(void* const* d_in, const int* in_sizes, int n_in,
                              void* d_out, int out_size) {
    const float* x    = (const float*)d_in[0];
    const float* w1   = (const float*)d_in[1];
    const float* b1   = (const float*)d_in[2];
    const float* w2   = (const float*)d_in[3];
    const float* b2   = (const float*)d_in[4];
    const float* eval = (const float*)d_in[5];
    const int*   erow = (const int*)d_in[6];
    const int*   ecol = (const int*)d_in[7];
    float* out = (float*)d_out;

    static cudaStream_t s_side = nullptr;
    static cudaEvent_t  ev_fork = nullptr, ev_csr = nullptr, ev_g0 = nullptr, ev_s0 = nullptr;
    static bool attr_set = false;
    if (!s_side) {
        cudaStreamCreateWithFlags(&s_side, cudaStreamNonBlocking);
        cudaEventCreateWithFlags(&ev_fork, cudaEventDisableTiming);
        cudaEventCreateWithFlags(&ev_csr,  cudaEventDisableTiming);
        cudaEventCreateWithFlags(&ev_g0,   cudaEventDisableTiming);
        cudaEventCreateWithFlags(&ev_s0,   cudaEventDisableTiming);
    }
    if (!attr_set) {
        cudaFuncSetAttribute(k_gemm1_mma, cudaFuncAttributeMaxDynamicSharedMemorySize, SMEM_MMA);
        attr_set = true;
    }

    // fork side stream
    cudaEventRecord(ev_fork, 0);
    cudaStreamWaitEvent(s_side, ev_fork, 0);

    // side: CSR build
    k_zero_cnt<<<256, 256, 0, s_side>>>();
    k_hist<<<2048, 256, 0, s_side>>>(erow);
    k_scan1<<<NSCANBLK, SCAN_B, 0, s_side>>>();
    k_scan2<<<1, 128, 0, s_side>>>();
    k_scan3<<<196, 512, 0, s_side>>>();
    k_scatter<<<2048, 256, 0, s_side>>>(eval, erow, ecol);
    cudaEventRecord(ev_csr, s_side);

    // main: dense transform, n-half 0
    k_split_w<<<(FIN * FH + 255) / 256, 256>>>(w1);
    k_gemm1_mma<<<NPAD / 128, 256, SMEM_MMA>>>(x, 0);
    cudaEventRecord(ev_g0, 0);

    // side: S0 (features 0-127) once CSR + G0 done; overlaps with G1 on main
    cudaStreamWaitEvent(s_side, ev_g0, 0);
    k_spmm1<<<NN, 64, 0, s_side>>>(b1, 0);
    cudaEventRecord(ev_s0, s_side);

    // main: n-half 1, then S1 (features 128-255)
    k_gemm1_mma<<<NPAD / 128, 256, SMEM_MMA>>>(x, 1);
    cudaStreamWaitEvent(0, ev_csr, 0);
    k_spmm1<<<NN, 64>>>(b1, 1);

    // join S0, finish layer 2
    cudaStreamWaitEvent(0, ev_s0, 0);
    k_gemm2<<<(NN + 255) / 256, 256>>>(w2);
    k_spmm2<<<NN, 64>>>(b2, out);
}